// round 6
// baseline (speedup 1.0000x reference)
#include <cuda_runtime.h>
#include <cstdint>

#define BATCH 16384
#define NEGK  20
#define NT    21              // 1 pos + 20 neg
#define NROWS 22              // + center row
#define DIM   128
#define ROW_BYTES 512
#define WPB   6               // warps per CTA
#define CTAS  148             // 1 CTA per SM, persistent
#define NWARPS (CTAS * WPB)   // 888 warps, grid-stride over batch
#define NSTAGE 3              // triple-buffer ring per warp
#define STAGE_BYTES (NROWS * ROW_BYTES)        // 11264
#define WARP_SMEM   (NSTAGE * STAGE_BYTES)     // 33792
#define SMEM_BYTES  (WPB * WARP_SMEM)          // 202752

__global__ void zero_out_kernel(float* out) { out[0] = 0.0f; }

__device__ __forceinline__ void cp16(uint32_t dst_smem, const void* src_gmem) {
    asm volatile("cp.async.cg.shared.global [%0], [%1], 16;"
                 :: "r"(dst_smem), "l"(src_gmem) : "memory");
}
__device__ __forceinline__ void cp_commit() {
    asm volatile("cp.async.commit_group;" ::: "memory");
}
template <int N>
__device__ __forceinline__ void cp_wait() {
    asm volatile("cp.async.wait_group %0;" :: "n"(N) : "memory");
}

extern __shared__ char smem_raw[];

// Lane 0 -> pos, lanes 1..20 -> neg, lane 21 -> center.
__device__ __forceinline__ int load_idx(int b, int lane,
                                        const int* __restrict__ pos,
                                        const int* __restrict__ neg,
                                        const int* __restrict__ center) {
    int v = 0;
    if (lane == 0)        v = pos[b];
    else if (lane < NT)   v = neg[b * NEGK + lane - 1];
    else if (lane == NT)  v = center[b];
    return v;
}

__global__ void __launch_bounds__(WPB * 32)
i2v_loss_kernel(const int* __restrict__ center,
                const int* __restrict__ pos,
                const int* __restrict__ neg,
                const float* __restrict__ W_in,
                const float* __restrict__ W_out,
                float* __restrict__ out)
{
    const unsigned FULL = 0xffffffffu;
    const int lane = threadIdx.x & 31;
    const int wid  = threadIdx.x >> 5;
    const int wgid = blockIdx.x * WPB + wid;   // global warp id

    const uint32_t sbase = (uint32_t)__cvta_generic_to_shared(smem_raw);
    const uint32_t wbase = sbase + wid * WARP_SMEM;

    // Issue all 22 row copies for one batch element into ring slot `slot`.
    auto issue = [&](int slot, int my_idx) {
        const uint32_t stage = wbase + slot * STAGE_BYTES;
        #pragma unroll
        for (int k = 0; k < NROWS; ++k) {
            const int idx = __shfl_sync(FULL, my_idx, k);
            const float* base = (k < NT) ? W_out : W_in;
            cp16(stage + k * ROW_BYTES + lane * 16,
                 base + (size_t)idx * DIM + 4 * lane);
        }
        cp_commit();
    };

    float lloss = 0.0f;

    int e = wgid;
    if (e < BATCH) {
        // ---- prologue: fill 2 stages ahead, prefetch index for stage 3 ----
        int idx0 = load_idx(e, lane, pos, neg, center);
        issue(0, idx0);
        int e1 = e + NWARPS;
        if (e1 < BATCH) {
            int idx1 = load_idx(e1, lane, pos, neg, center);
            issue(1, idx1);
        }
        int e2 = e + 2 * NWARPS;
        int idx2 = (e2 < BATCH) ? load_idx(e2, lane, pos, neg, center) : 0;

        int it = 0;   // iteration counter -> ring slot = it % 3
        while (e < BATCH) {
            const int slot = it % NSTAGE;
            const bool have1 = (e + NWARPS     < BATCH);
            const bool have2 = (e + 2 * NWARPS < BATCH);

            if (have2) {
                issue((it + 2) % NSTAGE, idx2);
                const int e3 = e + 3 * NWARPS;
                if (e3 < BATCH) idx2 = load_idx(e3, lane, pos, neg, center);
                cp_wait<2>();          // stage `it` complete, 2 still pending
            } else if (have1) {
                cp_wait<1>();
            } else {
                cp_wait<0>();
            }

            const uint32_t stage = wbase + slot * STAGE_BYTES;

            float4 c;
            asm volatile("ld.shared.v4.f32 {%0,%1,%2,%3}, [%4];"
                         : "=f"(c.x), "=f"(c.y), "=f"(c.z), "=f"(c.w)
                         : "r"(stage + NT * ROW_BYTES + lane * 16));

            float p[NT];
            #pragma unroll
            for (int k = 0; k < NT; ++k) {
                float4 v;
                asm volatile("ld.shared.v4.f32 {%0,%1,%2,%3}, [%4];"
                             : "=f"(v.x), "=f"(v.y), "=f"(v.z), "=f"(v.w)
                             : "r"(stage + k * ROW_BYTES + lane * 16));
                p[k] = c.x * v.x + c.y * v.y + c.z * v.z + c.w * v.w;
            }

            #pragma unroll
            for (int off = 16; off > 0; off >>= 1) {
                #pragma unroll
                for (int k = 0; k < NT; ++k)
                    p[k] += __shfl_xor_sync(FULL, p[k], off);
            }

            float mine = 0.0f;
            #pragma unroll
            for (int k = 0; k < NT; ++k)
                if (lane == k) mine = p[k];

            if (lane < NT) {
                const float s   = (lane == 0) ? mine : -mine;
                const float sig = 1.0f / (1.0f + __expf(-s));
                lloss += -logf(sig + 1e-10f);
            }

            e += NWARPS;
            ++it;
        }
    }

    // warp reduce accumulated loss, one atomic per warp
    #pragma unroll
    for (int off = 16; off > 0; off >>= 1)
        lloss += __shfl_xor_sync(FULL, lloss, off);

    if (lane == 0)
        atomicAdd(out, lloss * (1.0f / (float)BATCH));
}

extern "C" void kernel_launch(void* const* d_in, const int* in_sizes, int n_in,
                              void* d_out, int out_size)
{
    const int*   center = (const int*)  d_in[0];
    const int*   pos    = (const int*)  d_in[1];
    const int*   neg    = (const int*)  d_in[2];
    const float* W_in   = (const float*)d_in[3];
    const float* W_out  = (const float*)d_in[4];
    float* out = (float*)d_out;

    cudaFuncSetAttribute(i2v_loss_kernel,
                         cudaFuncAttributeMaxDynamicSharedMemorySize, SMEM_BYTES);

    zero_out_kernel<<<1, 1>>>(out);
    i2v_loss_kernel<<<CTAS, WPB * 32, SMEM_BYTES>>>(center, pos, neg,
                                                    W_in, W_out, out);
}

// round 7
// speedup vs baseline: 1.0601x; 1.0601x over previous
#include <cuda_runtime.h>
#include <cstdint>

#define BATCH 16384
#define NEGK  20
#define NT    21
#define DIM   128
#define ROW_BYTES 512
#define WPB   6                      // warps per CTA
#define CTAS  296                    // 2 CTAs/SM -> 12 warps/SM
#define NWARPS (CTAS * WPB)          // 1776
#define HROWS 11                     // rows per half-stage
#define HBYTES (HROWS * ROW_BYTES)   // 5632
#define NBUF  3                      // ring of 3 half-stage buffers / warp
#define WARP_SMEM (NBUF * HBYTES)    // 16896
#define SMEM_BYTES (WPB * WARP_SMEM) // 101376 (x2 CTAs = 202KB/SM)

__global__ void zero_out_kernel(float* out) { out[0] = 0.0f; }

__device__ __forceinline__ void cp16(uint32_t dst_smem, const void* src_gmem) {
    asm volatile("cp.async.cg.shared.global [%0], [%1], 16;"
                 :: "r"(dst_smem), "l"(src_gmem) : "memory");
}
__device__ __forceinline__ void cp_commit() {
    asm volatile("cp.async.commit_group;" ::: "memory");
}
__device__ __forceinline__ void wait_pend(int p) {
    if (p <= 0)      asm volatile("cp.async.wait_group 0;" ::: "memory");
    else if (p == 1) asm volatile("cp.async.wait_group 1;" ::: "memory");
    else             asm volatile("cp.async.wait_group 2;" ::: "memory");
}

extern __shared__ char smem_raw[];

__device__ __forceinline__ float4 lds128(uint32_t a) {
    float4 v;
    asm volatile("ld.shared.v4.f32 {%0,%1,%2,%3}, [%4];"
                 : "=f"(v.x), "=f"(v.y), "=f"(v.z), "=f"(v.w) : "r"(a));
    return v;
}

// lane 0 -> pos, lanes 1..20 -> neg targets 1..20, lane 21 -> center
__device__ __forceinline__ int load_idx(int b, int lane,
                                        const int* __restrict__ pos,
                                        const int* __restrict__ neg,
                                        const int* __restrict__ center) {
    int v = 0;
    if (lane == 0)        v = pos[b];
    else if (lane < NT)   v = neg[b * NEGK + lane - 1];
    else if (lane == NT)  v = center[b];
    return v;
}

__global__ void __launch_bounds__(WPB * 32)
i2v_loss_kernel(const int* __restrict__ center,
                const int* __restrict__ pos,
                const int* __restrict__ neg,
                const float* __restrict__ W_in,
                const float* __restrict__ W_out,
                float* __restrict__ out)
{
    const unsigned FULL = 0xffffffffu;
    const int lane = threadIdx.x & 31;
    const int wid  = threadIdx.x >> 5;
    const int wgid = blockIdx.x * WPB + wid;

    const uint32_t sbase = (uint32_t)__cvta_generic_to_shared(smem_raw);
    const uint32_t wbase = sbase + wid * WARP_SMEM;

    // half 0 (A): targets 0..9 in slots 0..9, center row in slot 10
    // half 1 (B): targets 10..20 in slots 0..10
    auto issue_half = [&](uint32_t stage, int my_idx, int half) {
        if (half == 0) {
            #pragma unroll
            for (int s = 0; s < 10; ++s) {
                const int idx = __shfl_sync(FULL, my_idx, s);
                cp16(stage + s * ROW_BYTES + lane * 16,
                     W_out + (size_t)idx * DIM + 4 * lane);
            }
            {
                const int idx = __shfl_sync(FULL, my_idx, NT);  // center
                cp16(stage + 10 * ROW_BYTES + lane * 16,
                     W_in + (size_t)idx * DIM + 4 * lane);
            }
        } else {
            #pragma unroll
            for (int s = 0; s < 11; ++s) {
                const int idx = __shfl_sync(FULL, my_idx, 10 + s);
                cp16(stage + s * ROW_BYTES + lane * 16,
                     W_out + (size_t)idx * DIM + 4 * lane);
            }
        }
        cp_commit();
    };

    // number of elements this warp owns (wgid < BATCH always; NWARPS=1776)
    const int n = (BATCH - 1 - wgid) / NWARPS + 1;

    // ---- prologue: groups 0,1,2 = A(0), B(0), A(1) -------------------------
    int idx0 = load_idx(wgid, lane, pos, neg, center);
    int idxn1 = (n > 1) ? load_idx(wgid + NWARPS, lane, pos, neg, center) : 0;

    issue_half(wbase + 0 * HBYTES, idx0, 0);                    // g0: A(0)
    if (n >= 1) issue_half(wbase + 1 * HBYTES, idx0, 1);        // g1: B(0)
    if (n >= 2) issue_half(wbase + 2 * HBYTES, idxn1, 0);       // g2: A(1)

    int idxn2 = (n > 2) ? load_idx(wgid + 2 * NWARPS, lane, pos, neg, center) : 0;

    float lloss = 0.0f;

    #pragma unroll 1
    for (int j = 0; j < n; ++j) {
        const int bufA = (2 * j) % NBUF;
        const int bufB = (2 * j + 1) % NBUF;

        // ---- consume A(j): targets 0..9 + center ---------------------------
        wait_pend(min(2, 2 * (n - j) - 1));
        const uint32_t stA = wbase + bufA * HBYTES;

        const float4 c = lds128(stA + 10 * ROW_BYTES + lane * 16);

        float pa[10];
        #pragma unroll
        for (int s = 0; s < 10; ++s) {
            const float4 v = lds128(stA + s * ROW_BYTES + lane * 16);
            pa[s] = c.x * v.x + c.y * v.y + c.z * v.z + c.w * v.w;
        }

        if (j + 1 < n)                          // g(2j+3) = B(j+1) -> bufA
            issue_half(wbase + bufA * HBYTES, idxn1, 1);

        #pragma unroll
        for (int off = 16; off > 0; off >>= 1) {
            #pragma unroll
            for (int s = 0; s < 10; ++s)
                pa[s] += __shfl_xor_sync(FULL, pa[s], off);
        }
        {
            float mine = 0.0f;
            #pragma unroll
            for (int s = 0; s < 10; ++s)
                if (lane == s) mine = pa[s];
            if (lane < 10) {
                const float arg = (lane == 0) ? -mine : mine;  // pos vs neg
                const float sig = 1.0f / (1.0f + __expf(arg));
                lloss += -logf(sig + 1e-10f);
            }
        }

        // ---- consume B(j): targets 10..20 ----------------------------------
        wait_pend(min(2, 2 * (n - j) - 2));
        const uint32_t stB = wbase + bufB * HBYTES;

        float pb[11];
        #pragma unroll
        for (int s = 0; s < 11; ++s) {
            const float4 v = lds128(stB + s * ROW_BYTES + lane * 16);
            pb[s] = c.x * v.x + c.y * v.y + c.z * v.z + c.w * v.w;
        }

        if (j + 2 < n)                          // g(2j+4) = A(j+2) -> bufB
            issue_half(wbase + bufB * HBYTES, idxn2, 0);

        #pragma unroll
        for (int off = 16; off > 0; off >>= 1) {
            #pragma unroll
            for (int s = 0; s < 11; ++s)
                pb[s] += __shfl_xor_sync(FULL, pb[s], off);
        }
        {
            float mine = 0.0f;
            #pragma unroll
            for (int s = 0; s < 11; ++s)
                if (lane == 10 + s) mine = pb[s];
            if (lane >= 10 && lane < NT) {
                const float sig = 1.0f / (1.0f + __expf(mine));  // all negative
                lloss += -logf(sig + 1e-10f);
            }
        }

        // ---- rotate index prefetch -----------------------------------------
        idxn1 = idxn2;
        if (j + 3 < n)
            idxn2 = load_idx(wgid + (j + 3) * NWARPS, lane, pos, neg, center);
    }

    #pragma unroll
    for (int off = 16; off > 0; off >>= 1)
        lloss += __shfl_xor_sync(FULL, lloss, off);

    if (lane == 0)
        atomicAdd(out, lloss * (1.0f / (float)BATCH));
}

extern "C" void kernel_launch(void* const* d_in, const int* in_sizes, int n_in,
                              void* d_out, int out_size)
{
    const int*   center = (const int*)  d_in[0];
    const int*   pos    = (const int*)  d_in[1];
    const int*   neg    = (const int*)  d_in[2];
    const float* W_in   = (const float*)d_in[3];
    const float* W_out  = (const float*)d_in[4];
    float* out = (float*)d_out;

    cudaFuncSetAttribute(i2v_loss_kernel,
                         cudaFuncAttributeMaxDynamicSharedMemorySize, SMEM_BYTES);

    zero_out_kernel<<<1, 1>>>(out);
    i2v_loss_kernel<<<CTAS, WPB * 32, SMEM_BYTES>>>(center, pos, neg,
                                                    W_in, W_out, out);
}

// round 8
// speedup vs baseline: 1.1393x; 1.0748x over previous
#include <cuda_runtime.h>
#include <cstdint>

#define BATCH 16384
#define NEGK  20
#define NT    21              // 1 pos + 20 neg
#define NROWS 22              // + center row
#define DIM   128
#define ROW_BYTES 512
#define WPB   5               // warps per CTA (10 warps/SM at 2 CTAs/SM)
#define CTAS  296             // 2 resident CTAs per SM, all 148 SMs balanced
#define NWARPS (CTAS * WPB)   // 1480 persistent warps, grid-stride over batch
#define STAGE_BYTES (NROWS * ROW_BYTES)   // 11264
#define WARP_SMEM   (2 * STAGE_BYTES)     // 22528 (double buffered)
#define SMEM_BYTES  (WPB * WARP_SMEM)     // 112640 (x2 CTAs = 225280 <= 228KB)

__global__ void zero_out_kernel(float* out) { out[0] = 0.0f; }

__device__ __forceinline__ void cp16(uint32_t dst_smem, const void* src_gmem) {
    asm volatile("cp.async.cg.shared.global [%0], [%1], 16;"
                 :: "r"(dst_smem), "l"(src_gmem) : "memory");
}
__device__ __forceinline__ void cp_commit() {
    asm volatile("cp.async.commit_group;" ::: "memory");
}
__device__ __forceinline__ void cp_wait1() {
    asm volatile("cp.async.wait_group 1;" ::: "memory");
}
__device__ __forceinline__ void cp_wait0() {
    asm volatile("cp.async.wait_group 0;" ::: "memory");
}

extern __shared__ char smem_raw[];

// Lane 0 -> pos, lanes 1..20 -> neg, lane 21 -> center.
__device__ __forceinline__ int load_idx(int b, int lane,
                                        const int* __restrict__ pos,
                                        const int* __restrict__ neg,
                                        const int* __restrict__ center) {
    int v = 0;
    if (lane == 0)        v = pos[b];
    else if (lane < NT)   v = neg[b * NEGK + lane - 1];
    else if (lane == NT)  v = center[b];
    return v;
}

__global__ void __launch_bounds__(WPB * 32)
i2v_loss_kernel(const int* __restrict__ center,
                const int* __restrict__ pos,
                const int* __restrict__ neg,
                const float* __restrict__ W_in,
                const float* __restrict__ W_out,
                float* __restrict__ out)
{
    const unsigned FULL = 0xffffffffu;
    const int lane = threadIdx.x & 31;
    const int wid  = threadIdx.x >> 5;
    const int wgid = blockIdx.x * WPB + wid;   // global warp id

    const uint32_t sbase = (uint32_t)__cvta_generic_to_shared(smem_raw);
    const uint32_t wbase = sbase + wid * WARP_SMEM;

    // Issue all 22 row copies for a batch element into stage buf (0/1).
    auto issue = [&](int buf, int my_idx) {
        const uint32_t stage = wbase + buf * STAGE_BYTES;
        #pragma unroll
        for (int k = 0; k < NROWS; ++k) {
            const int idx = __shfl_sync(FULL, my_idx, k);
            const float* base = (k < NT) ? W_out : W_in;
            cp16(stage + k * ROW_BYTES + lane * 16,
                 base + (size_t)idx * DIM + 4 * lane);
        }
        cp_commit();
    };

    float lloss = 0.0f;

    // Grid-stride software pipeline: element e in buf, e+NWARPS prefetching.
    int e = wgid;
    int buf = 0;
    if (e < BATCH) {
        int idx_cur = load_idx(e, lane, pos, neg, center);
        issue(buf, idx_cur);
        int nxt = e + NWARPS;
        int idx_nxt = (nxt < BATCH) ? load_idx(nxt, lane, pos, neg, center) : 0;

        while (e < BATCH) {
            const int has_next = (e + NWARPS < BATCH);
            if (has_next) {
                issue(buf ^ 1, idx_nxt);
                const int nn = e + 2 * NWARPS;
                if (nn < BATCH) idx_nxt = load_idx(nn, lane, pos, neg, center);
                cp_wait1();        // current stage done; next still in flight
            } else {
                cp_wait0();
            }

            const uint32_t stage = wbase + buf * STAGE_BYTES;

            float4 c;
            asm volatile("ld.shared.v4.f32 {%0,%1,%2,%3}, [%4];"
                         : "=f"(c.x), "=f"(c.y), "=f"(c.z), "=f"(c.w)
                         : "r"(stage + NT * ROW_BYTES + lane * 16));

            float p[NT];
            #pragma unroll
            for (int k = 0; k < NT; ++k) {
                float4 v;
                asm volatile("ld.shared.v4.f32 {%0,%1,%2,%3}, [%4];"
                             : "=f"(v.x), "=f"(v.y), "=f"(v.z), "=f"(v.w)
                             : "r"(stage + k * ROW_BYTES + lane * 16));
                p[k] = c.x * v.x + c.y * v.y + c.z * v.z + c.w * v.w;
            }

            #pragma unroll
            for (int off = 16; off > 0; off >>= 1) {
                #pragma unroll
                for (int k = 0; k < NT; ++k)
                    p[k] += __shfl_xor_sync(FULL, p[k], off);
            }

            float mine = 0.0f;
            #pragma unroll
            for (int k = 0; k < NT; ++k)
                if (lane == k) mine = p[k];

            if (lane < NT) {
                const float s   = (lane == 0) ? mine : -mine;
                const float sig = 1.0f / (1.0f + __expf(-s));
                lloss += -logf(sig + 1e-10f);
            }

            e += NWARPS;
            buf ^= 1;
        }
    }

    // warp reduce accumulated loss, one atomic per warp
    #pragma unroll
    for (int off = 16; off > 0; off >>= 1)
        lloss += __shfl_xor_sync(FULL, lloss, off);

    if (lane == 0)
        atomicAdd(out, lloss * (1.0f / (float)BATCH));
}

extern "C" void kernel_launch(void* const* d_in, const int* in_sizes, int n_in,
                              void* d_out, int out_size)
{
    const int*   center = (const int*)  d_in[0];
    const int*   pos    = (const int*)  d_in[1];
    const int*   neg    = (const int*)  d_in[2];
    const float* W_in   = (const float*)d_in[3];
    const float* W_out  = (const float*)d_in[4];
    float* out = (float*)d_out;

    cudaFuncSetAttribute(i2v_loss_kernel,
                         cudaFuncAttributeMaxDynamicSharedMemorySize, SMEM_BYTES);

    zero_out_kernel<<<1, 1>>>(out);
    i2v_loss_kernel<<<CTAS, WPB * 32, SMEM_BYTES>>>(center, pos, neg,
                                                    W_in, W_out, out);
}